// round 9
// baseline (speedup 1.0000x reference)
#include <cuda_runtime.h>
#include <cstdint>

// ---------------------------------------------------------------------------
// Problem constants
// ---------------------------------------------------------------------------
constexpr int B   = 2;
constexpr int S   = 2048;
constexpr int H   = 2048;
constexpr int NH  = 16;
constexpr int D   = 128;
constexpr int M   = B * S;     // 4096
constexpr int H3  = 3 * H;     // 6144
constexpr float SM_SCALE = 0.08838834764831845f;  // 1/sqrt(128)

// ---------------------------------------------------------------------------
// Scratch
// ---------------------------------------------------------------------------
__device__ float g_qkv[(size_t)M * H3];      // [4096, 6144]
__device__ float g_ctx[(size_t)M * H];       // [4096, 2048] (tf32-rounded)
__device__ float g_atf[(size_t)M * H];       // hidden, tf32-rounded
__device__ float g_wqkvt[(size_t)H3 * H];    // W_qkv^T [6144][2048], tf32
__device__ float g_woutt[(size_t)H * H];     // W_out^T [2048][2048], tf32

// ---------------------------------------------------------------------------
// Helpers (baseline PTX only — compiles at compute_100)
// ---------------------------------------------------------------------------
__device__ __forceinline__ uint32_t smem_u32(const void* p) {
    uint32_t a;
    asm("{ .reg .u64 t; cvta.to.shared.u64 t, %1; cvt.u32.u64 %0, t; }"
        : "=r"(a) : "l"(p));
    return a;
}
__device__ __forceinline__ float f2tf(float x) {
    uint32_t r;
    asm("cvt.rna.tf32.f32 %0, %1;" : "=r"(r) : "f"(x));
    return __uint_as_float(r);
}
__device__ __forceinline__ void mma8u(float* d, const uint32_t* a, const uint32_t* b) {
    asm volatile(
        "mma.sync.aligned.m16n8k8.row.col.f32.tf32.tf32.f32 "
        "{%0,%1,%2,%3}, {%4,%5,%6,%7}, {%8,%9}, {%0,%1,%2,%3};\n"
        : "+f"(d[0]), "+f"(d[1]), "+f"(d[2]), "+f"(d[3])
        : "r"(a[0]), "r"(a[1]), "r"(a[2]), "r"(a[3]), "r"(b[0]), "r"(b[1]));
}
__device__ __forceinline__ void ldm_x4(uint32_t* r, uint32_t addr) {
    asm volatile("ldmatrix.sync.aligned.m8n8.x4.shared.b16 {%0,%1,%2,%3}, [%4];"
                 : "=r"(r[0]), "=r"(r[1]), "=r"(r[2]), "=r"(r[3]) : "r"(addr));
}
__device__ __forceinline__ void cp_async16(void* smem, const void* gmem) {
    uint32_t s = (uint32_t)__cvta_generic_to_shared(smem);
    asm volatile("cp.async.cg.shared.global [%0], [%1], 16;\n" :: "r"(s), "l"(gmem));
}
__device__ __forceinline__ void cp_commit() { asm volatile("cp.async.commit_group;\n"); }
template <int N>
__device__ __forceinline__ void cp_wait() {
    asm volatile("cp.async.wait_group %0;\n" :: "n"(N));
}

// ---------------------------------------------------------------------------
// Prologue 1: elementwise tf32 rounding
// ---------------------------------------------------------------------------
__global__ void round_tf32_kernel(const float* __restrict__ in,
                                  float* __restrict__ out, int n4)
{
    int i = blockIdx.x * 256 + threadIdx.x;
    if (i < n4) {
        float4 v = reinterpret_cast<const float4*>(in)[i];
        v.x = f2tf(v.x); v.y = f2tf(v.y); v.z = f2tf(v.z); v.w = f2tf(v.w);
        reinterpret_cast<float4*>(out)[i] = v;
    }
}

// ---------------------------------------------------------------------------
// Prologue 2: W [K][N] -> Wt [N][K], tf32-rounded
// ---------------------------------------------------------------------------
__global__ void transpose_round_kernel(const float* __restrict__ W,
                                       float* __restrict__ Wt, int K, int N)
{
    __shared__ float t[32][33];
    const int n0 = blockIdx.x * 32, k0 = blockIdx.y * 32;
    const int tx = threadIdx.x, ty = threadIdx.y;
#pragma unroll
    for (int j = 0; j < 4; j++)
        t[ty + 8 * j][tx] = W[(size_t)(k0 + ty + 8 * j) * N + n0 + tx];
    __syncthreads();
#pragma unroll
    for (int j = 0; j < 4; j++)
        Wt[(size_t)(n0 + ty + 8 * j) * K + k0 + tx] = f2tf(t[tx][ty + 8 * j]);
}

// ---------------------------------------------------------------------------
// GEMM: C = A[M,K] @ Bt[N,K]^T + bias.  3-stage cp.async, ldmatrix, 1 bar/chunk.
// ---------------------------------------------------------------------------
constexpr int APAD = 36;
constexpr int GA   = 128 * APAD;             // floats per A tile
constexpr int GSTG = 2 * GA;                 // A + B per stage (9216 floats)
constexpr int GSMEM_BYTES = 3 * GSTG * 4;    // 110592 B

__global__ __launch_bounds__(128)
void gemm_ldm_kernel(const float* __restrict__ A,  int lda,
                     const float* __restrict__ Bt, int ldbt,
                     float* __restrict__ C,        int ldc,
                     int K, const float* __restrict__ bias)
{
    extern __shared__ __align__(16) float sg[];

    const int tid  = threadIdx.x;
    const int warp = tid >> 5, lane = tid & 31;
    const int wm = (warp >> 1) * 64, wn = (warp & 1) * 64;
    const int m0 = blockIdx.y * 128, n0 = blockIdx.x * 128;

    A  += (size_t)m0 * lda;
    Bt += (size_t)n0 * ldbt;
    C  += (size_t)m0 * ldc + n0;

    const int rowA = (lane & 7) + (lane & 8);
    const int colA = (lane & 16) ? 4 : 0;
    const int rowB = (lane & 7) + ((lane & 16) >> 1);
    const int colB = (lane & 8) ? 4 : 0;

    float acc[4][8][4];
#pragma unroll
    for (int mi = 0; mi < 4; mi++)
#pragma unroll
        for (int nj = 0; nj < 8; nj++)
#pragma unroll
            for (int r = 0; r < 4; r++) acc[mi][nj][r] = 0.0f;

    auto stage = [&](int kt, int buf) {
        float* dA = sg + buf * GSTG;
        float* dB = dA + GA;
        const int k0 = kt * 32;
#pragma unroll
        for (int j = 0; j < 8; j++) {
            int idx = tid + j * 128;
            int r = idx >> 3, c = (idx & 7) * 4;
            cp_async16(&dA[r * APAD + c], A + (size_t)r * lda + k0 + c);
        }
#pragma unroll
        for (int j = 0; j < 8; j++) {
            int idx = tid + j * 128;
            int r = idx >> 3, c = (idx & 7) * 4;
            cp_async16(&dB[r * APAD + c], Bt + (size_t)r * ldbt + k0 + c);
        }
        cp_commit();
    };

    const int KT = K / 32;
    stage(0, 0);
    stage(1, 1);

    for (int kt = 0; kt < KT; kt++) {
        if (kt + 1 < KT) cp_wait<1>(); else cp_wait<0>();
        __syncthreads();
        if (kt + 2 < KT) {
            int nb = kt + 2;
            stage(nb, nb % 3);
        }

        const float* cA = sg + (kt % 3) * GSTG;
        const float* cB = cA + GA;
        uint32_t aAdr[4], bAdr[4];
#pragma unroll
        for (int mi = 0; mi < 4; mi++)
            aAdr[mi] = smem_u32(cA + (wm + mi * 16 + rowA) * APAD + colA);
#pragma unroll
        for (int njp = 0; njp < 4; njp++)
            bAdr[njp] = smem_u32(cB + (wn + njp * 16 + rowB) * APAD + colB);

#pragma unroll
        for (int kk = 0; kk < 32; kk += 8) {
            uint32_t a[4][4], bfr[4][4];
#pragma unroll
            for (int mi = 0; mi < 4; mi++)   ldm_x4(a[mi],   aAdr[mi]  + kk * 4);
#pragma unroll
            for (int njp = 0; njp < 4; njp++) ldm_x4(bfr[njp], bAdr[njp] + kk * 4);
#pragma unroll
            for (int mi = 0; mi < 4; mi++)
#pragma unroll
                for (int nj = 0; nj < 8; nj++)
                    mma8u(acc[mi][nj], a[mi], &bfr[nj >> 1][(nj & 1) * 2]);
        }
    }

    // epilogue
#pragma unroll
    for (int mi = 0; mi < 4; mi++) {
#pragma unroll
        for (int nj = 0; nj < 8; nj++) {
            const int g = lane >> 2, t = lane & 3;
            const int row = wm + mi * 16 + g;
            const int col = wn + nj * 8 + 2 * t;
            const float b0 = bias ? bias[n0 + col]     : 0.0f;
            const float b1 = bias ? bias[n0 + col + 1] : 0.0f;
            *reinterpret_cast<float2*>(C + (size_t)row * ldc + col) =
                make_float2(acc[mi][nj][0] + b0, acc[mi][nj][1] + b1);
            *reinterpret_cast<float2*>(C + (size_t)(row + 8) * ldc + col) =
                make_float2(acc[mi][nj][2] + b0, acc[mi][nj][3] + b1);
        }
    }
}

// ---------------------------------------------------------------------------
// Fused flash attention, full-ldmatrix tf32 path.
// sQ [q][d], sKV: K [key][d] then V transposed [d][key], sP [q][key];
// all stride 132 (== 4 mod 32 -> conflict-free ldmatrix phases).
// ---------------------------------------------------------------------------
constexpr int FST = 132;
constexpr int FLASH_SMEM_FLOATS = 3 * 128 * FST + 128 + S;
constexpr int FLASH_SMEM_BYTES  = FLASH_SMEM_FLOATS * 4;   // ~206.5 KB

__global__ __launch_bounds__(256)
void flash_mma_kernel(const float* __restrict__ mask)
{
    extern __shared__ __align__(16) float sm[];
    float* sQ    = sm;
    float* sKV   = sQ  + 128 * FST;
    float* sP    = sKV + 128 * FST;
    float* sRow  = sP  + 128 * FST;
    float* sMask = sRow + 128;

    const int tid  = threadIdx.x;
    const int warp = tid >> 5, lane = tid & 31;
    const int g = lane >> 2, t = lane & 3;
    const int wm = (warp >> 2) * 64, wn = (warp & 3) * 32;

    const int rowA = (lane & 7) + (lane & 8);
    const int colA = (lane & 16) ? 4 : 0;
    const int rowB = (lane & 7) + ((lane & 16) >> 1);
    const int colB = (lane & 8) ? 4 : 0;

    const int z  = blockIdx.y;
    const int b  = z >> 4;
    const int h  = z & 15;
    const int q0 = blockIdx.x * 128;

    const float* __restrict__ Qg = g_qkv + (size_t)(b * S + q0) * H3 + h * D;

    // ---- load Q (tf32), mask, zero rowsums ----
#pragma unroll
    for (int i = tid; i < 4096; i += 256) {
        int r = i >> 5, c = (i & 31) * 4;
        float4 v = *reinterpret_cast<const float4*>(Qg + (size_t)r * H3 + c);
        v.x = f2tf(v.x); v.y = f2tf(v.y); v.z = f2tf(v.z); v.w = f2tf(v.w);
        *reinterpret_cast<float4*>(&sQ[r * FST + c]) = v;
    }
#pragma unroll
    for (int i = tid; i < S; i += 256) sMask[i] = mask[(size_t)b * S + i];
    if (tid < 128) sRow[tid] = 0.0f;

    // ldmatrix addresses (fixed buffers -> compute once)
    uint32_t aQAdr[4], aPAdr[4], bAdr[2];
#pragma unroll
    for (int mi = 0; mi < 4; mi++) {
        aQAdr[mi] = smem_u32(sQ + (wm + mi * 16 + rowA) * FST + colA);
        aPAdr[mi] = smem_u32(sP + (wm + mi * 16 + rowA) * FST + colA);
    }
#pragma unroll
    for (int njp = 0; njp < 2; njp++)
        bAdr[njp] = smem_u32(sKV + (wn + njp * 16 + rowB) * FST + colB);

    float oacc[4][4][4];
#pragma unroll
    for (int mi = 0; mi < 4; mi++)
#pragma unroll
        for (int nj = 0; nj < 4; nj++)
#pragma unroll
            for (int r = 0; r < 4; r++) oacc[mi][nj][r] = 0.0f;

    for (int jt = 0; jt < S / 128; jt++) {
        const int n0 = jt * 128;
        const float* __restrict__ Kg = g_qkv + (size_t)(b * S + n0) * H3 + H     + h * D;
        const float* __restrict__ Vg = g_qkv + (size_t)(b * S + n0) * H3 + 2 * H + h * D;

        // ---- stage K [key][d] (natural), tf32 ----
#pragma unroll
        for (int i = tid; i < 4096; i += 256) {
            int r = i >> 5, c = (i & 31) * 4;
            float4 v = *reinterpret_cast<const float4*>(Kg + (size_t)r * H3 + c);
            v.x = f2tf(v.x); v.y = f2tf(v.y); v.z = f2tf(v.z); v.w = f2tf(v.w);
            *reinterpret_cast<float4*>(&sKV[r * FST + c]) = v;
        }
        __syncthreads();

        // ---- S = Q @ K^T (ldmatrix both operands) ----
        float sacc[4][4][4];
#pragma unroll
        for (int mi = 0; mi < 4; mi++)
#pragma unroll
            for (int nj = 0; nj < 4; nj++)
#pragma unroll
                for (int r = 0; r < 4; r++) sacc[mi][nj][r] = 0.0f;

#pragma unroll
        for (int kk = 0; kk < D; kk += 8) {
            uint32_t a[4][4], bfr[2][4];
#pragma unroll
            for (int mi = 0; mi < 4; mi++)   ldm_x4(a[mi],   aQAdr[mi] + kk * 4);
#pragma unroll
            for (int njp = 0; njp < 2; njp++) ldm_x4(bfr[njp], bAdr[njp] + kk * 4);
#pragma unroll
            for (int mi = 0; mi < 4; mi++)
#pragma unroll
                for (int nj = 0; nj < 4; nj++)
                    mma8u(sacc[mi][nj], a[mi], &bfr[nj >> 1][(nj & 1) * 2]);
        }
        __syncthreads();   // all warps done reading K -> sKV reusable for V^T

        // ---- stage V transposed: sVt[d][key], tf32.
        //      4 coalesced LDG.32 down a key-quad + 1 conflict-free STS.128 ----
#pragma unroll
        for (int i = tid; i < 4096; i += 256) {
            int kgrp = i >> 7;                         // key quad 0..31
            int d    = ((i >> 5) & 3) * 32 + (i & 31); // 0..127 (lane-contig)
            const float* src = Vg + (size_t)(4 * kgrp) * H3 + d;
            float4 o;
            o.x = f2tf(src[0]);
            o.y = f2tf(src[(size_t)H3]);
            o.z = f2tf(src[(size_t)2 * H3]);
            o.w = f2tf(src[(size_t)3 * H3]);
            *reinterpret_cast<float4*>(&sKV[d * FST + 4 * kgrp]) = o;
        }

        // ---- P = exp(S*scale + mask); store tf32 P; rowsums ----
#pragma unroll
        for (int mi = 0; mi < 4; mi++) {
            const int r0 = wm + mi * 16 + g;
            float rp0 = 0.0f, rp1 = 0.0f;
#pragma unroll
            for (int nj = 0; nj < 4; nj++) {
                const int col = wn + nj * 8 + 2 * t;
                const float m0v = sMask[n0 + col];
                const float m1v = sMask[n0 + col + 1];
                float p00 = __expf(fmaf(sacc[mi][nj][0], SM_SCALE, m0v));
                float p01 = __expf(fmaf(sacc[mi][nj][1], SM_SCALE, m1v));
                float p10 = __expf(fmaf(sacc[mi][nj][2], SM_SCALE, m0v));
                float p11 = __expf(fmaf(sacc[mi][nj][3], SM_SCALE, m1v));
                rp0 += p00 + p01;
                rp1 += p10 + p11;
                *reinterpret_cast<float2*>(&sP[r0 * FST + col]) =
                    make_float2(f2tf(p00), f2tf(p01));
                *reinterpret_cast<float2*>(&sP[(r0 + 8) * FST + col]) =
                    make_float2(f2tf(p10), f2tf(p11));
            }
            rp0 += __shfl_xor_sync(0xffffffffu, rp0, 1);
            rp0 += __shfl_xor_sync(0xffffffffu, rp0, 2);
            rp1 += __shfl_xor_sync(0xffffffffu, rp1, 1);
            rp1 += __shfl_xor_sync(0xffffffffu, rp1, 2);
            if (t == 0) {
                atomicAdd(&sRow[r0], rp0);
                atomicAdd(&sRow[r0 + 8], rp1);
            }
        }
        __syncthreads();   // P + V^T visible

        // ---- O += P @ V (ldmatrix both; bAdr same formula on sVt) ----
#pragma unroll
        for (int kk = 0; kk < 128; kk += 8) {
            uint32_t a[4][4], bfr[2][4];
#pragma unroll
            for (int mi = 0; mi < 4; mi++)   ldm_x4(a[mi],   aPAdr[mi] + kk * 4);
#pragma unroll
            for (int njp = 0; njp < 2; njp++) ldm_x4(bfr[njp], bAdr[njp] + kk * 4);
#pragma unroll
            for (int mi = 0; mi < 4; mi++)
#pragma unroll
                for (int nj = 0; nj < 4; nj++)
                    mma8u(oacc[mi][nj], a[mi], &bfr[nj >> 1][(nj & 1) * 2]);
        }
        __syncthreads();   // before next jt restages sKV / sP
    }

    // ---- epilogue: normalize, store ctx tf32-rounded ----
#pragma unroll
    for (int mi = 0; mi < 4; mi++) {
        const int r0 = wm + mi * 16 + g;
        const float inv0 = 1.0f / sRow[r0];
        const float inv1 = 1.0f / sRow[r0 + 8];
#pragma unroll
        for (int nj = 0; nj < 4; nj++) {
            const int col = wn + nj * 8 + 2 * t;
            float* dst = g_ctx + (size_t)(b * S + q0 + r0) * H + h * D + col;
            *reinterpret_cast<float2*>(dst) =
                make_float2(f2tf(oacc[mi][nj][0] * inv0), f2tf(oacc[mi][nj][1] * inv0));
            *reinterpret_cast<float2*>(dst + (size_t)8 * H) =
                make_float2(f2tf(oacc[mi][nj][2] * inv1), f2tf(oacc[mi][nj][3] * inv1));
        }
    }
}

// ---------------------------------------------------------------------------
// Launch
// ---------------------------------------------------------------------------
extern "C" void kernel_launch(void* const* d_in, const int* in_sizes, int n_in,
                              void* d_out, int out_size)
{
    const float* hidden = nullptr;
    const float* mask   = nullptr;
    const float* W_qkv  = nullptr;
    const float* b_qkv  = nullptr;
    const float* W_out  = nullptr;
    const float* b_out  = nullptr;

    for (int i = 0; i < n_in; i++) {
        switch (in_sizes[i]) {
            case 8388608:  hidden = (const float*)d_in[i]; break;
            case 4096:     mask   = (const float*)d_in[i]; break;
            case 12582912: W_qkv  = (const float*)d_in[i]; break;
            case 6144:     b_qkv  = (const float*)d_in[i]; break;
            case 4194304:  W_out  = (const float*)d_in[i]; break;
            case 2048:     b_out  = (const float*)d_in[i]; break;
            default: break;
        }
    }
    float* out = (float*)d_out;

    cudaFuncSetAttribute(flash_mma_kernel,
                         cudaFuncAttributeMaxDynamicSharedMemorySize,
                         FLASH_SMEM_BYTES);
    cudaFuncSetAttribute(gemm_ldm_kernel,
                         cudaFuncAttributeMaxDynamicSharedMemorySize,
                         GSMEM_BYTES);

    float* qkv_ptr;   cudaGetSymbolAddress((void**)&qkv_ptr,  g_qkv);
    float* ctx_ptr;   cudaGetSymbolAddress((void**)&ctx_ptr,  g_ctx);
    float* atf_ptr;   cudaGetSymbolAddress((void**)&atf_ptr,  g_atf);
    float* wqkvt_ptr; cudaGetSymbolAddress((void**)&wqkvt_ptr, g_wqkvt);
    float* woutt_ptr; cudaGetSymbolAddress((void**)&woutt_ptr, g_woutt);

    round_tf32_kernel<<<(M * H / 4 + 255) / 256, 256>>>(hidden, atf_ptr, M * H / 4);
    transpose_round_kernel<<<dim3(H3 / 32, H / 32), dim3(32, 8)>>>(W_qkv, wqkvt_ptr, H, H3);
    transpose_round_kernel<<<dim3(H / 32, H / 32), dim3(32, 8)>>>(W_out, woutt_ptr, H, H);

    gemm_ldm_kernel<<<dim3(H3 / 128, M / 128), 128, GSMEM_BYTES>>>(
        atf_ptr, H, wqkvt_ptr, H, qkv_ptr, H3, H, b_qkv);

    flash_mma_kernel<<<dim3(S / 128, B * NH), 256, FLASH_SMEM_BYTES>>>(mask);

    gemm_ldm_kernel<<<dim3(H / 128, M / 128), 128, GSMEM_BYTES>>>(
        ctx_ptr, H, woutt_ptr, H, out, H, H, b_out);
}

// round 10
// speedup vs baseline: 1.2710x; 1.2710x over previous
#include <cuda_runtime.h>
#include <cstdint>

// ---------------------------------------------------------------------------
// Problem constants
// ---------------------------------------------------------------------------
constexpr int B   = 2;
constexpr int S   = 2048;
constexpr int H   = 2048;
constexpr int NH  = 16;
constexpr int D   = 128;
constexpr int M   = B * S;     // 4096
constexpr int H3  = 3 * H;     // 6144
constexpr float SM_SCALE = 0.08838834764831845f;  // 1/sqrt(128)

// ---------------------------------------------------------------------------
// Scratch
// ---------------------------------------------------------------------------
__device__ float g_qkv[(size_t)M * H3];      // [4096, 6144]
__device__ float g_ctx[(size_t)M * H];       // [4096, 2048] (tf32-rounded)
__device__ float g_atf[(size_t)M * H];       // hidden, tf32-rounded
__device__ float g_wqkvt[(size_t)H3 * H];    // W_qkv^T [6144][2048], tf32
__device__ float g_woutt[(size_t)H * H];     // W_out^T [2048][2048], tf32

// ---------------------------------------------------------------------------
// Helpers (baseline PTX only — compiles at compute_100)
// ---------------------------------------------------------------------------
__device__ __forceinline__ uint32_t smem_u32(const void* p) {
    uint32_t a;
    asm("{ .reg .u64 t; cvta.to.shared.u64 t, %1; cvt.u32.u64 %0, t; }"
        : "=r"(a) : "l"(p));
    return a;
}
__device__ __forceinline__ float f2tf(float x) {
    uint32_t r;
    asm("cvt.rna.tf32.f32 %0, %1;" : "=r"(r) : "f"(x));
    return __uint_as_float(r);
}
__device__ __forceinline__ void mma8u(float* d, const uint32_t* a, const uint32_t* b) {
    asm volatile(
        "mma.sync.aligned.m16n8k8.row.col.f32.tf32.tf32.f32 "
        "{%0,%1,%2,%3}, {%4,%5,%6,%7}, {%8,%9}, {%0,%1,%2,%3};\n"
        : "+f"(d[0]), "+f"(d[1]), "+f"(d[2]), "+f"(d[3])
        : "r"(a[0]), "r"(a[1]), "r"(a[2]), "r"(a[3]), "r"(b[0]), "r"(b[1]));
}
// float operand form (flash kernel)
__device__ __forceinline__ void mma8(float* d, const float* a, const float* b) {
    asm volatile(
        "mma.sync.aligned.m16n8k8.row.col.f32.tf32.tf32.f32 "
        "{%0,%1,%2,%3}, {%4,%5,%6,%7}, {%8,%9}, {%0,%1,%2,%3};\n"
        : "+f"(d[0]), "+f"(d[1]), "+f"(d[2]), "+f"(d[3])
        : "r"(__float_as_uint(a[0])), "r"(__float_as_uint(a[1])),
          "r"(__float_as_uint(a[2])), "r"(__float_as_uint(a[3])),
          "r"(__float_as_uint(b[0])), "r"(__float_as_uint(b[1])));
}
__device__ __forceinline__ void ldm_x4(uint32_t* r, uint32_t addr) {
    asm volatile("ldmatrix.sync.aligned.m8n8.x4.shared.b16 {%0,%1,%2,%3}, [%4];"
                 : "=r"(r[0]), "=r"(r[1]), "=r"(r[2]), "=r"(r[3]) : "r"(addr));
}
__device__ __forceinline__ void cp_async16(void* smem, const void* gmem) {
    uint32_t s = (uint32_t)__cvta_generic_to_shared(smem);
    asm volatile("cp.async.cg.shared.global [%0], [%1], 16;\n" :: "r"(s), "l"(gmem));
}
__device__ __forceinline__ void cp_commit() { asm volatile("cp.async.commit_group;\n"); }
template <int N>
__device__ __forceinline__ void cp_wait() {
    asm volatile("cp.async.wait_group %0;\n" :: "n"(N));
}

// ---------------------------------------------------------------------------
// Prologue 1: elementwise tf32 rounding (hidden -> g_atf)
// ---------------------------------------------------------------------------
__global__ void round_tf32_kernel(const float* __restrict__ in,
                                  float* __restrict__ out, int n4)
{
    int i = blockIdx.x * 256 + threadIdx.x;
    if (i < n4) {
        float4 v = reinterpret_cast<const float4*>(in)[i];
        v.x = f2tf(v.x); v.y = f2tf(v.y); v.z = f2tf(v.z); v.w = f2tf(v.w);
        reinterpret_cast<float4*>(out)[i] = v;
    }
}

// ---------------------------------------------------------------------------
// Prologue 2: W [K][N] -> Wt [N][K], tf32-rounded.  block (32,8)
// ---------------------------------------------------------------------------
__global__ void transpose_round_kernel(const float* __restrict__ W,
                                       float* __restrict__ Wt, int K, int N)
{
    __shared__ float t[32][33];
    const int n0 = blockIdx.x * 32, k0 = blockIdx.y * 32;
    const int tx = threadIdx.x, ty = threadIdx.y;
#pragma unroll
    for (int j = 0; j < 4; j++)
        t[ty + 8 * j][tx] = W[(size_t)(k0 + ty + 8 * j) * N + n0 + tx];
    __syncthreads();
#pragma unroll
    for (int j = 0; j < 4; j++)
        Wt[(size_t)(n0 + ty + 8 * j) * K + k0 + tx] = f2tf(t[tx][ty + 8 * j]);
}

// ---------------------------------------------------------------------------
// GEMM: C[128,128/block] = A[M,K] @ Bt[N,K]^T + bias.  A,Bt pre-rounded tf32.
// 128 threads (4 warps, 2x2 of 64x64). cp.async 2-stage; ldmatrix fragments.
// __launch_bounds__(128, 3): 3 CTAs/SM (smem 3x73728=221KB, regs 3x128x168=64512)
// ---------------------------------------------------------------------------
constexpr int APAD = 36;
constexpr int GA   = 128 * APAD;            // floats per A stage
constexpr int GSTG = 2 * GA;                // A + B per stage
constexpr int GSMEM_BYTES = 2 * GSTG * 4;   // 73728 B

__global__ __launch_bounds__(128, 3)
void gemm_ldm_kernel(const float* __restrict__ A,  int lda,
                     const float* __restrict__ Bt, int ldbt,
                     float* __restrict__ C,        int ldc,
                     int K, const float* __restrict__ bias)
{
    extern __shared__ __align__(16) float sg[];

    const int tid  = threadIdx.x;
    const int warp = tid >> 5, lane = tid & 31;
    const int wm = (warp >> 1) * 64, wn = (warp & 1) * 64;
    const int m0 = blockIdx.y * 128, n0 = blockIdx.x * 128;

    A  += (size_t)m0 * lda;
    Bt += (size_t)n0 * ldbt;
    C  += (size_t)m0 * ldc + n0;

    // ldmatrix per-lane source mapping (A-pattern for both; Bt is [n][k])
    const int rowA = (lane & 7) + (lane & 8);
    const int colA = (lane & 16) ? 4 : 0;
    const int rowB = (lane & 7) + ((lane & 16) >> 1);
    const int colB = (lane & 8) ? 4 : 0;

    float acc[4][8][4];
#pragma unroll
    for (int mi = 0; mi < 4; mi++)
#pragma unroll
        for (int nj = 0; nj < 8; nj++)
#pragma unroll
            for (int r = 0; r < 4; r++) acc[mi][nj][r] = 0.0f;

    auto stage = [&](int kt, int buf) {
        float* dA = sg + buf * GSTG;
        float* dB = dA + GA;
        const int k0 = kt * 32;
#pragma unroll
        for (int j = 0; j < 8; j++) {       // A: 1024 16B chunks / 128 thr
            int idx = tid + j * 128;
            int r = idx >> 3, c = (idx & 7) * 4;
            cp_async16(&dA[r * APAD + c], A + (size_t)r * lda + k0 + c);
        }
#pragma unroll
        for (int j = 0; j < 8; j++) {       // B: rows of Bt (n-major)
            int idx = tid + j * 128;
            int r = idx >> 3, c = (idx & 7) * 4;
            cp_async16(&dB[r * APAD + c], Bt + (size_t)r * ldbt + k0 + c);
        }
        cp_commit();
    };

    stage(0, 0);
    const int KT = K / 32;

    for (int kt = 0; kt < KT; kt++) {
        const int buf = kt & 1;
        if (kt + 1 < KT) { stage(kt + 1, buf ^ 1); cp_wait<1>(); }
        else             { cp_wait<0>(); }
        __syncthreads();

        const float* cA = sg + buf * GSTG;
        const float* cB = cA + GA;
        uint32_t aAdr[4], bAdr[4];
#pragma unroll
        for (int mi = 0; mi < 4; mi++)
            aAdr[mi] = smem_u32(cA + (wm + mi * 16 + rowA) * APAD + colA);
#pragma unroll
        for (int njp = 0; njp < 4; njp++)
            bAdr[njp] = smem_u32(cB + (wn + njp * 16 + rowB) * APAD + colB);

#pragma unroll
        for (int kk = 0; kk < 32; kk += 8) {
            uint32_t a[4][4], bfr[4][4];
#pragma unroll
            for (int mi = 0; mi < 4; mi++)   ldm_x4(a[mi],   aAdr[mi]  + kk * 4);
#pragma unroll
            for (int njp = 0; njp < 4; njp++) ldm_x4(bfr[njp], bAdr[njp] + kk * 4);
#pragma unroll
            for (int mi = 0; mi < 4; mi++)
#pragma unroll
                for (int nj = 0; nj < 8; nj++)
                    mma8u(acc[mi][nj], a[mi], &bfr[nj >> 1][(nj & 1) * 2]);
        }
        __syncthreads();
    }

    // epilogue
#pragma unroll
    for (int mi = 0; mi < 4; mi++) {
#pragma unroll
        for (int nj = 0; nj < 8; nj++) {
            const int g = lane >> 2, t = lane & 3;
            const int row = wm + mi * 16 + g;
            const int col = wn + nj * 8 + 2 * t;
            const float b0 = bias ? bias[n0 + col]     : 0.0f;
            const float b1 = bias ? bias[n0 + col + 1] : 0.0f;
            *reinterpret_cast<float2*>(C + (size_t)row * ldc + col) =
                make_float2(acc[mi][nj][0] + b0, acc[mi][nj][1] + b1);
            *reinterpret_cast<float2*>(C + (size_t)(row + 8) * ldc + col) =
                make_float2(acc[mi][nj][2] + b0, acc[mi][nj][3] + b1);
        }
    }
}

// ---------------------------------------------------------------------------
// Fused flash attention, tf32 mma.sync (round-8 verified version; ctx tf32)
// ---------------------------------------------------------------------------
constexpr int QP = 132, KSTR = 132, VSTR = 136, PP = 132;
constexpr int FLASH_SMEM_FLOATS = 128 * QP + 128 * VSTR + 128 * PP + 128 + S;
constexpr int FLASH_SMEM_BYTES  = FLASH_SMEM_FLOATS * 4;

__global__ __launch_bounds__(256)
void flash_mma_kernel(const float* __restrict__ mask)
{
    extern __shared__ __align__(16) float sm[];
    float* sQ    = sm;
    float* sKV   = sQ  + 128 * QP;
    float* sP    = sKV + 128 * VSTR;
    float* sRow  = sP  + 128 * PP;
    float* sMask = sRow + 128;

    const int tid  = threadIdx.x;
    const int warp = tid >> 5, lane = tid & 31;
    const int g = lane >> 2, t = lane & 3;
    const int wm = (warp >> 2) * 64, wn = (warp & 3) * 32;

    const int z  = blockIdx.y;
    const int b  = z >> 4;
    const int h  = z & 15;
    const int q0 = blockIdx.x * 128;

    const float* __restrict__ Qg = g_qkv + (size_t)(b * S + q0) * H3 + h * D;

#pragma unroll
    for (int i = tid; i < 4096; i += 256) {
        int r = i >> 5, c = (i & 31) * 4;
        float4 v = *reinterpret_cast<const float4*>(Qg + (size_t)r * H3 + c);
        v.x = f2tf(v.x); v.y = f2tf(v.y); v.z = f2tf(v.z); v.w = f2tf(v.w);
        *reinterpret_cast<float4*>(&sQ[r * QP + c]) = v;
    }
#pragma unroll
    for (int i = tid; i < S; i += 256) sMask[i] = mask[(size_t)b * S + i];
    if (tid < 128) sRow[tid] = 0.0f;

    float oacc[4][4][4];
#pragma unroll
    for (int mi = 0; mi < 4; mi++)
#pragma unroll
        for (int nj = 0; nj < 4; nj++)
#pragma unroll
            for (int r = 0; r < 4; r++) oacc[mi][nj][r] = 0.0f;

    for (int jt = 0; jt < S / 128; jt++) {
        const int n0 = jt * 128;
        const float* __restrict__ Kg = g_qkv + (size_t)(b * S + n0) * H3 + H     + h * D;
        const float* __restrict__ Vg = g_qkv + (size_t)(b * S + n0) * H3 + 2 * H + h * D;

#pragma unroll
        for (int i = tid; i < 4096; i += 256) {
            int r = i >> 5, c = (i & 31) * 4;
            float4 v = *reinterpret_cast<const float4*>(Kg + (size_t)r * H3 + c);
            v.x = f2tf(v.x); v.y = f2tf(v.y); v.z = f2tf(v.z); v.w = f2tf(v.w);
            *reinterpret_cast<float4*>(&sKV[r * KSTR + c]) = v;
        }
        __syncthreads();

        float sacc[4][4][4];
#pragma unroll
        for (int mi = 0; mi < 4; mi++)
#pragma unroll
            for (int nj = 0; nj < 4; nj++)
#pragma unroll
                for (int r = 0; r < 4; r++) sacc[mi][nj][r] = 0.0f;

#pragma unroll
        for (int kk = 0; kk < D; kk += 8) {
            float af[4][4], bf[4][2];
#pragma unroll
            for (int mi = 0; mi < 4; mi++) {
                const float* base = &sQ[(wm + mi * 16 + g) * QP + kk];
                af[mi][0] = base[t];
                af[mi][1] = base[8 * QP + t];
                af[mi][2] = base[t + 4];
                af[mi][3] = base[8 * QP + t + 4];
            }
#pragma unroll
            for (int nj = 0; nj < 4; nj++) {
                const int key = wn + nj * 8 + g;
                bf[nj][0] = sKV[key * KSTR + kk + t];
                bf[nj][1] = sKV[key * KSTR + kk + t + 4];
            }
#pragma unroll
            for (int mi = 0; mi < 4; mi++)
#pragma unroll
                for (int nj = 0; nj < 4; nj++)
                    mma8(sacc[mi][nj], af[mi], bf[nj]);
        }
        __syncthreads();

#pragma unroll
        for (int i = tid; i < 4096; i += 256) {
            int r = i >> 5, c = (i & 31) * 4;
            float4 v = *reinterpret_cast<const float4*>(Vg + (size_t)r * H3 + c);
            v.x = f2tf(v.x); v.y = f2tf(v.y); v.z = f2tf(v.z); v.w = f2tf(v.w);
            *reinterpret_cast<float4*>(&sKV[r * VSTR + c]) = v;
        }

#pragma unroll
        for (int mi = 0; mi < 4; mi++) {
            const int r0 = wm + mi * 16 + g;
            float rp0 = 0.0f, rp1 = 0.0f;
#pragma unroll
            for (int nj = 0; nj < 4; nj++) {
                const int col = wn + nj * 8 + 2 * t;
                const float m0v = sMask[n0 + col];
                const float m1v = sMask[n0 + col + 1];
                float p00 = __expf(fmaf(sacc[mi][nj][0], SM_SCALE, m0v));
                float p01 = __expf(fmaf(sacc[mi][nj][1], SM_SCALE, m1v));
                float p10 = __expf(fmaf(sacc[mi][nj][2], SM_SCALE, m0v));
                float p11 = __expf(fmaf(sacc[mi][nj][3], SM_SCALE, m1v));
                rp0 += p00 + p01;
                rp1 += p10 + p11;
                *reinterpret_cast<float2*>(&sP[r0 * PP + col]) =
                    make_float2(f2tf(p00), f2tf(p01));
                *reinterpret_cast<float2*>(&sP[(r0 + 8) * PP + col]) =
                    make_float2(f2tf(p10), f2tf(p11));
            }
            rp0 += __shfl_xor_sync(0xffffffffu, rp0, 1);
            rp0 += __shfl_xor_sync(0xffffffffu, rp0, 2);
            rp1 += __shfl_xor_sync(0xffffffffu, rp1, 1);
            rp1 += __shfl_xor_sync(0xffffffffu, rp1, 2);
            if (t == 0) {
                atomicAdd(&sRow[r0], rp0);
                atomicAdd(&sRow[r0 + 8], rp1);
            }
        }
        __syncthreads();

#pragma unroll
        for (int kk = 0; kk < 128; kk += 8) {
            float af[4][4], bf[4][2];
#pragma unroll
            for (int mi = 0; mi < 4; mi++) {
                const float* base = &sP[(wm + mi * 16 + g) * PP + kk];
                af[mi][0] = base[t];
                af[mi][1] = base[8 * PP + t];
                af[mi][2] = base[t + 4];
                af[mi][3] = base[8 * PP + t + 4];
            }
#pragma unroll
            for (int nj = 0; nj < 4; nj++) {
                const int col = wn + nj * 8 + g;
                bf[nj][0] = sKV[(kk + t) * VSTR + col];
                bf[nj][1] = sKV[(kk + t + 4) * VSTR + col];
            }
#pragma unroll
            for (int mi = 0; mi < 4; mi++)
#pragma unroll
                for (int nj = 0; nj < 4; nj++)
                    mma8(oacc[mi][nj], af[mi], bf[nj]);
        }
        __syncthreads();
    }

    // ctx stored tf32-rounded (out-proj GEMM consumes pre-rounded A)
#pragma unroll
    for (int mi = 0; mi < 4; mi++) {
        const int r0 = wm + mi * 16 + g;
        const float inv0 = 1.0f / sRow[r0];
        const float inv1 = 1.0f / sRow[r0 + 8];
#pragma unroll
        for (int nj = 0; nj < 4; nj++) {
            const int col = wn + nj * 8 + 2 * t;
            float* dst = g_ctx + (size_t)(b * S + q0 + r0) * H + h * D + col;
            *reinterpret_cast<float2*>(dst) =
                make_float2(f2tf(oacc[mi][nj][0] * inv0), f2tf(oacc[mi][nj][1] * inv0));
            *reinterpret_cast<float2*>(dst + (size_t)8 * H) =
                make_float2(f2tf(oacc[mi][nj][2] * inv1), f2tf(oacc[mi][nj][3] * inv1));
        }
    }
}

// ---------------------------------------------------------------------------
// Launch
// ---------------------------------------------------------------------------
extern "C" void kernel_launch(void* const* d_in, const int* in_sizes, int n_in,
                              void* d_out, int out_size)
{
    const float* hidden = nullptr;
    const float* mask   = nullptr;
    const float* W_qkv  = nullptr;
    const float* b_qkv  = nullptr;
    const float* W_out  = nullptr;
    const float* b_out  = nullptr;

    for (int i = 0; i < n_in; i++) {
        switch (in_sizes[i]) {
            case 8388608:  hidden = (const float*)d_in[i]; break;
            case 4096:     mask   = (const float*)d_in[i]; break;
            case 12582912: W_qkv  = (const float*)d_in[i]; break;
            case 6144:     b_qkv  = (const float*)d_in[i]; break;
            case 4194304:  W_out  = (const float*)d_in[i]; break;
            case 2048:     b_out  = (const float*)d_in[i]; break;
            default: break;
        }
    }
    float* out = (float*)d_out;

    cudaFuncSetAttribute(flash_mma_kernel,
                         cudaFuncAttributeMaxDynamicSharedMemorySize,
                         FLASH_SMEM_BYTES);
    cudaFuncSetAttribute(gemm_ldm_kernel,
                         cudaFuncAttributeMaxDynamicSharedMemorySize,
                         GSMEM_BYTES);

    float* qkv_ptr;   cudaGetSymbolAddress((void**)&qkv_ptr,  g_qkv);
    float* ctx_ptr;   cudaGetSymbolAddress((void**)&ctx_ptr,  g_ctx);
    float* atf_ptr;   cudaGetSymbolAddress((void**)&atf_ptr,  g_atf);
    float* wqkvt_ptr; cudaGetSymbolAddress((void**)&wqkvt_ptr, g_wqkvt);
    float* woutt_ptr; cudaGetSymbolAddress((void**)&woutt_ptr, g_woutt);

    round_tf32_kernel<<<(M * H / 4 + 255) / 256, 256>>>(hidden, atf_ptr, M * H / 4);
    transpose_round_kernel<<<dim3(H3 / 32, H / 32), dim3(32, 8)>>>(W_qkv, wqkvt_ptr, H, H3);
    transpose_round_kernel<<<dim3(H / 32, H / 32), dim3(32, 8)>>>(W_out, woutt_ptr, H, H);

    gemm_ldm_kernel<<<dim3(H3 / 128, M / 128), 128, GSMEM_BYTES>>>(
        atf_ptr, H, wqkvt_ptr, H, qkv_ptr, H3, H, b_qkv);

    flash_mma_kernel<<<dim3(S / 128, B * NH), 256, FLASH_SMEM_BYTES>>>(mask);

    gemm_ldm_kernel<<<dim3(H / 128, M / 128), 128, GSMEM_BYTES>>>(
        ctx_ptr, H, woutt_ptr, H, out, H, H, b_out);
}